// round 1
// baseline (speedup 1.0000x reference)
#include <cuda_runtime.h>
#include <stdint.h>

// Problem constants
#define BN 4      // batch
#define DD 81     // feature dim
#define KK 2048   // mixture components
#define ND 4      // box dims

#define MT 96     // padded M (81 -> 96)
#define NT 128    // GEMM N tile
#define KC 16     // GEMM k chunk per stage
#define KSLICE 4  // split-K factor
#define KSEG (KK / KSLICE)  // 512 k per block

// ---------------- scratch (static device globals; no runtime alloc) ----------------
__device__ float g_w[BN * KK];                    // pi_m * prod(sig)
__device__ float g_sig2[BN * ND * KK];            // sig^2
__device__ float g_rinv[BN * KK];                 // 1 / rowsum[p]
__device__ float g_lh[(size_t)BN * KK * KK];      // unnormalized likelihood [b][p][m]  (64 MiB)
__device__ float g_part[(size_t)KSLICE * BN * MT * KK];  // split-K partials

// ---------------- packed fp32x2 FMA (sm_100+) ----------------
__device__ __forceinline__ unsigned long long ffma2(unsigned long long a,
                                                    unsigned long long b,
                                                    unsigned long long c) {
    unsigned long long d;
    asm("fma.rn.f32x2 %0, %1, %2, %3;" : "=l"(d) : "l"(a), "l"(b), "l"(c));
    return d;
}

// ---------------- K1: per-component weights + sig^2 ----------------
__global__ void prep_kernel(const float* __restrict__ pi,
                            const float* __restrict__ sig) {
    int i = blockIdx.x * 256 + threadIdx.x;
    if (i >= BN * KK) return;
    int b = i / KK, k = i - b * KK;
    float prod = 1.0f;
#pragma unroll
    for (int n = 0; n < ND; n++) {
        float s = sig[(b * ND + n) * KK + k];
        g_sig2[(b * ND + n) * KK + k] = s * s;
        prod *= s;
    }
    g_w[i] = pi[i] * prod;   // pi is (B,1,K) -> [b*KK + k]
}

// ---------------- K2: lh matrix + row sums ----------------
// Each block: 8 consecutive p rows, full m range. 256 threads.
__global__ __launch_bounds__(256) void lh_kernel(const float* __restrict__ mu) {
    const int rows_per_b = KK / 8;
    int b  = blockIdx.x / rows_per_b;
    int p0 = (blockIdx.x - b * rows_per_b) * 8;

    __shared__ float smup[8][ND];
    if (threadIdx.x < 8 * ND) {
        int j = threadIdx.x / ND, n = threadIdx.x - j * ND;
        smup[j][n] = mu[(b * ND + n) * KK + p0 + j];
    }
    __syncthreads();

    float mup[8][ND];
#pragma unroll
    for (int j = 0; j < 8; j++)
#pragma unroll
        for (int n = 0; n < ND; n++) mup[j][n] = smup[j][n];

    const float* mub = mu + (size_t)b * ND * KK;
    const float* s2b = g_sig2 + (size_t)b * ND * KK;
    const float* wb  = g_w + (size_t)b * KK;
    float* lhb = g_lh + (size_t)b * KK * KK + (size_t)p0 * KK;

    float acc[8];
#pragma unroll
    for (int j = 0; j < 8; j++) acc[j] = 0.0f;

    for (int m = threadIdx.x; m < KK; m += 256) {
        float mm0 = mub[0 * KK + m], mm1 = mub[1 * KK + m];
        float mm2 = mub[2 * KK + m], mm3 = mub[3 * KK + m];
        float s0 = s2b[0 * KK + m], s1 = s2b[1 * KK + m];
        float s2 = s2b[2 * KK + m], s3 = s2b[3 * KK + m];
        float wm = wb[m];
#pragma unroll
        for (int j = 0; j < 8; j++) {
            float d0 = mup[j][0] - mm0;
            float d1 = mup[j][1] - mm1;
            float d2 = mup[j][2] - mm2;
            float d3 = mup[j][3] - mm3;
            float q0 = fmaf(d0, d0, s0);
            float q1 = fmaf(d1, d1, s1);
            float q2 = fmaf(d2, d2, s2);
            float q3 = fmaf(d3, d3, s3);
            float q = (q0 * q1) * (q2 * q3);
            float v = __fdividef(wm, q);
            acc[j] += v;
            lhb[(size_t)j * KK + m] = v;
        }
    }

    // block-reduce the 8 row sums
    __shared__ float red[8][9];
    int lane = threadIdx.x & 31, wid = threadIdx.x >> 5;
#pragma unroll
    for (int j = 0; j < 8; j++) {
        float v = acc[j];
#pragma unroll
        for (int o = 16; o > 0; o >>= 1) v += __shfl_xor_sync(0xffffffffu, v, o);
        if (lane == 0) red[wid][j] = v;
    }
    __syncthreads();
    if (threadIdx.x < 8) {
        float s = 0.0f;
#pragma unroll
        for (int w = 0; w < 8; w++) s += red[w][threadIdx.x];
        g_rinv[b * KK + p0 + threadIdx.x] = 1.0f / s;
    }
}

// ---------------- K3: split-K fp32x2 GEMM:  part = (x * rinv) @ lh ----------------
// grid: (KK/NT, KSLICE, BN), 256 threads, CTA tile 96x128, thread tile 6x8.
__global__ __launch_bounds__(256) void gemm_kernel(const float* __restrict__ x) {
    __shared__ __align__(16) float2 As[KC][98];  // A values pre-duplicated (v,v); row stride 98 (even)
    __shared__ __align__(16) float  Bs[KC][NT];

    int b     = blockIdx.z;
    int n0    = blockIdx.x * NT;
    int pbase = blockIdx.y * KSEG;
    int tid   = threadIdx.x;
    int tm = tid >> 4;        // 0..15 -> m rows [tm*6, tm*6+6)
    int tn = tid & 15;        // 0..15 -> n cols {tn*4..+3} U {64+tn*4..+3}

    unsigned long long acc[6][4];
#pragma unroll
    for (int i = 0; i < 6; i++)
#pragma unroll
        for (int j = 0; j < 4; j++) acc[i][j] = 0ULL;

    const float* xb    = x + (size_t)b * DD * KK;
    const float* rinvb = g_rinv + (size_t)b * KK;
    const float* lhb   = g_lh + (size_t)b * KK * KK;

    for (int stage = 0; stage < KSEG / KC; ++stage) {
        int kbase = pbase + stage * KC;
        // stage A: 16x96 elements, x * rinv, zero-pad rows >= 81, duplicate into pairs
#pragma unroll
        for (int e = 0; e < 6; e++) {
            int idx = tid + 256 * e;
            int k = idx & 15, m = idx >> 4;
            float v = 0.0f;
            if (m < DD) v = xb[(size_t)m * KK + kbase + k] * rinvb[kbase + k];
            As[k][m] = make_float2(v, v);
        }
        // stage B: 16x128 floats, 2 float4 per thread, fully coalesced
#pragma unroll
        for (int e = 0; e < 2; e++) {
            int idx = tid + 256 * e;
            int k = idx >> 5, c = (idx & 31) << 2;
            float4 v = *(const float4*)(lhb + (size_t)(kbase + k) * KK + n0 + c);
            *(float4*)&Bs[k][c] = v;
        }
        __syncthreads();

#pragma unroll
        for (int k = 0; k < KC; k++) {
            ulonglong2 a01 = *(const ulonglong2*)&As[k][tm * 6 + 0];
            ulonglong2 a23 = *(const ulonglong2*)&As[k][tm * 6 + 2];
            ulonglong2 a45 = *(const ulonglong2*)&As[k][tm * 6 + 4];
            ulonglong2 b01 = *(const ulonglong2*)&Bs[k][tn * 4];
            ulonglong2 b23 = *(const ulonglong2*)&Bs[k][64 + tn * 4];
            unsigned long long a[6] = {a01.x, a01.y, a23.x, a23.y, a45.x, a45.y};
#pragma unroll
            for (int i = 0; i < 6; i++) {
                acc[i][0] = ffma2(a[i], b01.x, acc[i][0]);
                acc[i][1] = ffma2(a[i], b01.y, acc[i][1]);
                acc[i][2] = ffma2(a[i], b23.x, acc[i][2]);
                acc[i][3] = ffma2(a[i], b23.y, acc[i][3]);
            }
        }
        __syncthreads();
    }

    // epilogue: write partial tile to g_part[slice][b][m][n]
    float* pp = g_part + (((size_t)blockIdx.y * BN + b) * MT) * KK;
#pragma unroll
    for (int i = 0; i < 6; i++) {
        int m = tm * 6 + i;
        float* row = pp + (size_t)m * KK + n0;
        float2 p0 = *(float2*)&acc[i][0];
        float2 p1 = *(float2*)&acc[i][1];
        float2 p2 = *(float2*)&acc[i][2];
        float2 p3 = *(float2*)&acc[i][3];
        float4 lo = make_float4(p0.x, p0.y, p1.x, p1.y);
        float4 hi = make_float4(p2.x, p2.y, p3.x, p3.y);
        *(float4*)(row + tn * 4)      = lo;
        *(float4*)(row + 64 + tn * 4) = hi;
    }
}

// ---------------- K4: deterministic split-K reduction into d_out ----------------
__global__ void reduce_kernel(float* __restrict__ y) {
    int i = blockIdx.x * 256 + threadIdx.x;
    if (i >= BN * DD * KK) return;
    int b = i / (DD * KK);
    int r = i - b * (DD * KK);
    int d = r / KK;
    int n = r - d * KK;
    size_t base = ((size_t)b * MT + d) * KK + n;
    float s = 0.0f;
#pragma unroll
    for (int sl = 0; sl < KSLICE; sl++)
        s += g_part[(size_t)sl * BN * MT * KK + base];
    y[i] = s;
}

// ---------------- launch ----------------
extern "C" void kernel_launch(void* const* d_in, const int* in_sizes, int n_in,
                              void* d_out, int out_size) {
    const float* x   = (const float*)d_in[0];  // (B, D, K)
    const float* pi  = (const float*)d_in[1];  // (B, 1, K)
    const float* mu  = (const float*)d_in[2];  // (B, ND, K)
    const float* sig = (const float*)d_in[3];  // (B, ND, K)
    float* y = (float*)d_out;                  // (B, D, K)

    prep_kernel<<<(BN * KK + 255) / 256, 256>>>(pi, sig);
    lh_kernel<<<BN * (KK / 8), 256>>>(mu);
    gemm_kernel<<<dim3(KK / NT, KSLICE, BN), 256>>>(x);
    reduce_kernel<<<(BN * DD * KK + 255) / 256, 256>>>(y);
}

// round 3
// speedup vs baseline: 1.7194x; 1.7194x over previous
#include <cuda_runtime.h>
#include <stdint.h>

// ---------------- problem constants ----------------
#define BN 4
#define DD 81
#define KK 2048
#define ND 4

// ---------------- GEMM config ----------------
#define MPAD 96             // padded M (81 -> 96)
#define NTILE 128           // n per CTA
#define KCH 32              // k per stage
#define KSPLIT 2
#define KSEG (KK / KSPLIT)  // 1024
#define NSTG (KSEG / KCH)   // 32
#define ASTRIDE 104         // smem f32 stride for A rows (bank-conflict-free frags)
#define BSTRIDE 136         // smem f32 stride for B rows
#define ABYTES (KCH * ASTRIDE * 4)
#define BBYTES (KCH * BSTRIDE * 4)
#define DYN_SMEM (2 * (ABYTES + BBYTES))

// ---------------- static device scratch ----------------
__device__ float g_w[BN * KK];
__device__ float g_sig2[BN * ND * KK];
__device__ float g_rinv[BN * KK];
__device__ float g_lh[(size_t)BN * KK * KK];              // tf32-rounded f32 [b][p][m]
__device__ float g_A[(size_t)BN * KK * MPAD];             // tf32-rounded x'^T [b][k][m]
__device__ float g_part[(size_t)KSPLIT * BN * MPAD * KK]; // split-K partials

// ---------------- helpers ----------------
__device__ __forceinline__ float to_tf32(float v) {
    float r;
    asm("cvt.rna.tf32.f32 %0, %1;" : "=f"(r) : "f"(v));
    return r;
}
__device__ __forceinline__ uint32_t smem_u32(const void* p) {
    uint32_t a;
    asm("{ .reg .u64 t; cvta.to.shared.u64 t, %1; cvt.u32.u64 %0, t; }" : "=r"(a) : "l"(p));
    return a;
}
__device__ __forceinline__ void cpasync16(uint32_t dst, const void* src) {
    asm volatile("cp.async.cg.shared.global [%0], [%1], 16;" :: "r"(dst), "l"(src));
}
#define CP_COMMIT() asm volatile("cp.async.commit_group;" ::: "memory")
#define CP_WAIT(n)  asm volatile("cp.async.wait_group %0;" :: "n"(n) : "memory")

__device__ __forceinline__ void mma_tf32(float* d, const uint32_t* a, const uint32_t* b) {
    asm volatile(
        "mma.sync.aligned.m16n8k8.row.col.f32.tf32.tf32.f32 "
        "{%0,%1,%2,%3}, {%4,%5,%6,%7}, {%8,%9}, {%0,%1,%2,%3};"
        : "+f"(d[0]), "+f"(d[1]), "+f"(d[2]), "+f"(d[3])
        : "r"(a[0]), "r"(a[1]), "r"(a[2]), "r"(a[3]), "r"(b[0]), "r"(b[1]));
}

// ---------------- K1: per-component weights + sig^2 ----------------
__global__ void prep_kernel(const float* __restrict__ pi,
                            const float* __restrict__ sig) {
    int i = blockIdx.x * 256 + threadIdx.x;
    if (i >= BN * KK) return;
    int b = i / KK, k = i - b * KK;
    float prod = 1.0f;
#pragma unroll
    for (int n = 0; n < ND; n++) {
        float s = sig[(b * ND + n) * KK + k];
        g_sig2[(b * ND + n) * KK + k] = s * s;
        prod *= s;
    }
    g_w[i] = pi[i] * prod;
}

// ---------------- K2: lh matrix (tf32-rounded) + row sums ----------------
__global__ __launch_bounds__(256) void lh_kernel(const float* __restrict__ mu) {
    const int rows_per_b = KK / 8;
    int b  = blockIdx.x / rows_per_b;
    int p0 = (blockIdx.x - b * rows_per_b) * 8;

    __shared__ float smup[8][ND];
    if (threadIdx.x < 8 * ND) {
        int j = threadIdx.x / ND, n = threadIdx.x - j * ND;
        smup[j][n] = mu[(b * ND + n) * KK + p0 + j];
    }
    __syncthreads();

    float mup[8][ND];
#pragma unroll
    for (int j = 0; j < 8; j++)
#pragma unroll
        for (int n = 0; n < ND; n++) mup[j][n] = smup[j][n];

    const float* mub = mu + (size_t)b * ND * KK;
    const float* s2b = g_sig2 + (size_t)b * ND * KK;
    const float* wb  = g_w + (size_t)b * KK;
    float* lhb = g_lh + (size_t)b * KK * KK + (size_t)p0 * KK;

    float acc[8];
#pragma unroll
    for (int j = 0; j < 8; j++) acc[j] = 0.0f;

    for (int m = threadIdx.x; m < KK; m += 256) {
        float mm0 = mub[0 * KK + m], mm1 = mub[1 * KK + m];
        float mm2 = mub[2 * KK + m], mm3 = mub[3 * KK + m];
        float s0 = s2b[0 * KK + m], s1 = s2b[1 * KK + m];
        float s2 = s2b[2 * KK + m], s3 = s2b[3 * KK + m];
        float wm = wb[m];
#pragma unroll
        for (int j = 0; j < 8; j++) {
            float d0 = mup[j][0] - mm0;
            float d1 = mup[j][1] - mm1;
            float d2 = mup[j][2] - mm2;
            float d3 = mup[j][3] - mm3;
            float q0 = fmaf(d0, d0, s0);
            float q1 = fmaf(d1, d1, s1);
            float q2 = fmaf(d2, d2, s2);
            float q3 = fmaf(d3, d3, s3);
            float q = (q0 * q1) * (q2 * q3);
            float v = __fdividef(wm, q);
            acc[j] += v;
            lhb[(size_t)j * KK + m] = to_tf32(v);
        }
    }

    __shared__ float red[8][9];
    int lane = threadIdx.x & 31, wid = threadIdx.x >> 5;
#pragma unroll
    for (int j = 0; j < 8; j++) {
        float v = acc[j];
#pragma unroll
        for (int o = 16; o > 0; o >>= 1) v += __shfl_xor_sync(0xffffffffu, v, o);
        if (lane == 0) red[wid][j] = v;
    }
    __syncthreads();
    if (threadIdx.x < 8) {
        float s = 0.0f;
#pragma unroll
        for (int w = 0; w < 8; w++) s += red[w][threadIdx.x];
        g_rinv[b * KK + p0 + threadIdx.x] = 1.0f / s;
    }
}

// ---------------- K3: A = (x * rinv)^T, tf32-rounded, zero-padded to 96 rows ----------------
// grid (KK/32, MPAD/32, BN), block (32, 8). 32x32 smem transpose tiles.
__global__ void aprep_kernel(const float* __restrict__ x) {
    __shared__ float t[32][33];
    int b = blockIdx.z, k0 = blockIdx.x * 32, m0 = blockIdx.y * 32;
    int tx = threadIdx.x, ty = threadIdx.y;

    float rv = g_rinv[b * KK + k0 + tx];
#pragma unroll
    for (int r = 0; r < 4; r++) {
        int m = m0 + r * 8 + ty;
        float v = 0.0f;
        if (m < DD) v = x[((size_t)b * DD + m) * KK + k0 + tx] * rv;
        t[r * 8 + ty][tx] = to_tf32(v);
    }
    __syncthreads();
#pragma unroll
    for (int r = 0; r < 4; r++) {
        int k = k0 + r * 8 + ty;
        g_A[((size_t)b * KK + k) * MPAD + m0 + tx] = t[tx][r * 8 + ty];
    }
}

// ---------------- K4: tf32 mma.sync GEMM: part = A^T-staged x' @ lh ----------------
// grid (KK/NTILE, KSPLIT, BN), 256 threads (8 warps = 2M x 4N).
__global__ __launch_bounds__(256, 1) void gemm_mma() {
    extern __shared__ char dsm[];
    float* As[2] = { (float*)dsm, (float*)(dsm + ABYTES + BBYTES) };
    float* Bs[2] = { (float*)(dsm + ABYTES), (float*)(dsm + 2 * ABYTES + BBYTES) };
    uint32_t sbase = smem_u32(dsm);
    uint32_t aoff[2] = { 0u, (uint32_t)(ABYTES + BBYTES) };
    uint32_t boff[2] = { (uint32_t)ABYTES, (uint32_t)(2 * ABYTES + BBYTES) };

    int tid = threadIdx.x, wid = tid >> 5, lane = tid & 31;
    int nt = blockIdx.x, ks = blockIdx.y, b = blockIdx.z;
    int n0 = nt * NTILE;
    int kbase0 = ks * KSEG;

    int warpM = wid >> 2, warpN = wid & 3;
    int mbase = warpM * 48, nbase = warpN * 32;
    int g = lane >> 2, c = lane & 3;

    const float* gA = g_A + (size_t)b * KK * MPAD;
    const float* gB = g_lh + (size_t)b * KK * KK + n0;

    float acc[3][4][4];
#pragma unroll
    for (int i = 0; i < 3; i++)
#pragma unroll
        for (int j = 0; j < 4; j++)
#pragma unroll
            for (int q = 0; q < 4; q++) acc[i][j][q] = 0.0f;

    // stage loader: 3 A-chunks + 4 B-chunks of 16B per thread
    auto stage = [&](int s, int buf) {
        int kb = kbase0 + s * KCH;
#pragma unroll
        for (int e = 0; e < 3; e++) {
            int i = tid + 256 * e;           // 0..767
            int k = i / 24, cc = i - k * 24; // 24 x 16B = 96 floats
            cpasync16(sbase + aoff[buf] + (k * ASTRIDE + cc * 4) * 4,
                      gA + (size_t)(kb + k) * MPAD + cc * 4);
        }
#pragma unroll
        for (int e = 0; e < 4; e++) {
            int i = tid + 256 * e;           // 0..1023
            int k = i >> 5, cc = i & 31;     // 32 x 16B = 128 floats
            cpasync16(sbase + boff[buf] + (k * BSTRIDE + cc * 4) * 4,
                      gB + (size_t)(kb + k) * KK + cc * 4);
        }
        CP_COMMIT();
    };

    stage(0, 0);

    for (int s = 0; s < NSTG; s++) {
        int buf = s & 1;
        if (s + 1 < NSTG) {
            stage(s + 1, buf ^ 1);
            CP_WAIT(1);
        } else {
            CP_WAIT(0);
        }
        __syncthreads();

        const float* A = As[buf];
        const float* B = Bs[buf];
#pragma unroll
        for (int kk = 0; kk < KCH / 8; kk++) {
            uint32_t af[3][4], bf[4][2];
            const float* Ar0 = A + (kk * 8 + c) * ASTRIDE;
            const float* Ar1 = A + (kk * 8 + c + 4) * ASTRIDE;
            const float* Br0 = B + (kk * 8 + c) * BSTRIDE;
            const float* Br1 = B + (kk * 8 + c + 4) * BSTRIDE;
#pragma unroll
            for (int mf = 0; mf < 3; mf++) {
                int m0i = mbase + mf * 16 + g;
                af[mf][0] = __float_as_uint(Ar0[m0i]);
                af[mf][1] = __float_as_uint(Ar0[m0i + 8]);
                af[mf][2] = __float_as_uint(Ar1[m0i]);
                af[mf][3] = __float_as_uint(Ar1[m0i + 8]);
            }
#pragma unroll
            for (int nf = 0; nf < 4; nf++) {
                int n0i = nbase + nf * 8 + g;
                bf[nf][0] = __float_as_uint(Br0[n0i]);
                bf[nf][1] = __float_as_uint(Br1[n0i]);
            }
#pragma unroll
            for (int mf = 0; mf < 3; mf++)
#pragma unroll
                for (int nf = 0; nf < 4; nf++)
                    mma_tf32(acc[mf][nf], af[mf], bf[nf]);
        }
        __syncthreads();
    }

    // epilogue: write partials
    float* pp = g_part + ((size_t)(ks * BN + b) * MPAD) * KK + n0;
    int tig = lane & 3;
#pragma unroll
    for (int mf = 0; mf < 3; mf++) {
        int r0 = mbase + mf * 16 + g;
#pragma unroll
        for (int nf = 0; nf < 4; nf++) {
            int cc = nbase + nf * 8 + tig * 2;
            *(float2*)(pp + (size_t)r0 * KK + cc)       = make_float2(acc[mf][nf][0], acc[mf][nf][1]);
            *(float2*)(pp + (size_t)(r0 + 8) * KK + cc) = make_float2(acc[mf][nf][2], acc[mf][nf][3]);
        }
    }
}

// ---------------- K5: deterministic split-K reduce ----------------
__global__ void reduce_kernel(float* __restrict__ y) {
    int i = blockIdx.x * 256 + threadIdx.x;
    if (i >= BN * DD * KK) return;
    int b = i / (DD * KK);
    int r = i - b * (DD * KK);
    int d = r / KK;
    int m = r - d * KK;
    size_t o = ((size_t)b * MPAD + d) * KK + m;
    y[i] = g_part[o] + g_part[(size_t)BN * MPAD * KK + o];
}

// ---------------- launch ----------------
extern "C" void kernel_launch(void* const* d_in, const int* in_sizes, int n_in,
                              void* d_out, int out_size) {
    const float* x   = (const float*)d_in[0];  // (B, D, K)
    const float* pi  = (const float*)d_in[1];  // (B, 1, K)
    const float* mu  = (const float*)d_in[2];  // (B, ND, K)
    const float* sig = (const float*)d_in[3];  // (B, ND, K)
    float* y = (float*)d_out;                  // (B, D, K)

    cudaFuncSetAttribute(gemm_mma, cudaFuncAttributeMaxDynamicSharedMemorySize, DYN_SMEM);

    prep_kernel<<<(BN * KK + 255) / 256, 256>>>(pi, sig);
    lh_kernel<<<BN * (KK / 8), 256>>>(mu);
    aprep_kernel<<<dim3(KK / 32, MPAD / 32, BN), dim3(32, 8)>>>(x);
    gemm_mma<<<dim3(KK / NTILE, KSPLIT, BN), 256, DYN_SMEM>>>();
    reduce_kernel<<<(BN * DD * KK + 255) / 256, 256>>>(y);
}

// round 4
// speedup vs baseline: 2.0304x; 1.1809x over previous
#include <cuda_runtime.h>
#include <stdint.h>

// ---------------- problem constants ----------------
#define BN 4
#define DD 81
#define KK 2048
#define ND 4

// ---------------- GEMM config ----------------
#define MPAD 96             // padded M (81 -> 96)
#define NTILE 128           // n per CTA
#define KCH 32              // k per stage
#define KSPLIT 2
#define KSEG (KK / KSPLIT)  // 1024
#define NSTG (KSEG / KCH)   // 32
#define NPIPE 3             // cp.async pipeline depth
#define BSTRIDE 136         // smem f32 row stride for B (conflict-free frag reads)
#define ABYTES (KCH / 8 * 6 * 512)      // 12288: frag-packed A stage
#define BBYTES (KCH * BSTRIDE * 4)      // 17408
#define STGBYTES (ABYTES + BBYTES)      // 29696
#define DYN_SMEM (NPIPE * STGBYTES)

// ---------------- static device scratch ----------------
__device__ float g_w[BN * KK];
__device__ float g_sig2[BN * ND * KK];
__device__ float g_rinv[BN * KK];
__device__ float g_lh[(size_t)BN * KK * KK];              // tf32-rounded f32 [b][p][m]
__device__ float g_A[(size_t)BN * (KK / 8) * 6 * 128];    // frag-packed A [b][kb][mfg][lane*4]
__device__ float g_part[(size_t)KSPLIT * BN * MPAD * KK]; // split-K partials

// ---------------- helpers ----------------
__device__ __forceinline__ float to_tf32(float v) {
    float r;
    asm("cvt.rna.tf32.f32 %0, %1;" : "=f"(r) : "f"(v));
    return r;
}
__device__ __forceinline__ uint32_t smem_u32(const void* p) {
    uint32_t a;
    asm("{ .reg .u64 t; cvta.to.shared.u64 t, %1; cvt.u32.u64 %0, t; }" : "=r"(a) : "l"(p));
    return a;
}
__device__ __forceinline__ void cpasync16(uint32_t dst, const void* src) {
    asm volatile("cp.async.cg.shared.global [%0], [%1], 16;" :: "r"(dst), "l"(src));
}
#define CP_COMMIT() asm volatile("cp.async.commit_group;" ::: "memory")
#define CP_WAIT(n)  asm volatile("cp.async.wait_group %0;" :: "n"(n) : "memory")

__device__ __forceinline__ void mma_tf32(float* d, const uint32_t* a, const uint32_t* b) {
    asm volatile(
        "mma.sync.aligned.m16n8k8.row.col.f32.tf32.tf32.f32 "
        "{%0,%1,%2,%3}, {%4,%5,%6,%7}, {%8,%9}, {%0,%1,%2,%3};"
        : "+f"(d[0]), "+f"(d[1]), "+f"(d[2]), "+f"(d[3])
        : "r"(a[0]), "r"(a[1]), "r"(a[2]), "r"(a[3]), "r"(b[0]), "r"(b[1]));
}

// ---------------- K1: per-component weights + sig^2 ----------------
__global__ void prep_kernel(const float* __restrict__ pi,
                            const float* __restrict__ sig) {
    int i = blockIdx.x * 256 + threadIdx.x;
    if (i >= BN * KK) return;
    int b = i / KK, k = i - b * KK;
    float prod = 1.0f;
#pragma unroll
    for (int n = 0; n < ND; n++) {
        float s = sig[(b * ND + n) * KK + k];
        g_sig2[(b * ND + n) * KK + k] = s * s;
        prod *= s;
    }
    g_w[i] = pi[i] * prod;
}

// ---------------- K2: lh matrix (tf32-rounded) + row sums ----------------
__global__ __launch_bounds__(256) void lh_kernel(const float* __restrict__ mu) {
    const int rows_per_b = KK / 8;
    int b  = blockIdx.x / rows_per_b;
    int p0 = (blockIdx.x - b * rows_per_b) * 8;

    __shared__ float smup[8][ND];
    if (threadIdx.x < 8 * ND) {
        int j = threadIdx.x / ND, n = threadIdx.x - j * ND;
        smup[j][n] = mu[(b * ND + n) * KK + p0 + j];
    }
    __syncthreads();

    float mup[8][ND];
#pragma unroll
    for (int j = 0; j < 8; j++)
#pragma unroll
        for (int n = 0; n < ND; n++) mup[j][n] = smup[j][n];

    const float* mub = mu + (size_t)b * ND * KK;
    const float* s2b = g_sig2 + (size_t)b * ND * KK;
    const float* wb  = g_w + (size_t)b * KK;
    float* lhb = g_lh + (size_t)b * KK * KK + (size_t)p0 * KK;

    float acc[8];
#pragma unroll
    for (int j = 0; j < 8; j++) acc[j] = 0.0f;

    for (int m = threadIdx.x; m < KK; m += 256) {
        float mm0 = mub[0 * KK + m], mm1 = mub[1 * KK + m];
        float mm2 = mub[2 * KK + m], mm3 = mub[3 * KK + m];
        float s0 = s2b[0 * KK + m], s1 = s2b[1 * KK + m];
        float s2 = s2b[2 * KK + m], s3 = s2b[3 * KK + m];
        float wm = wb[m];
#pragma unroll
        for (int j = 0; j < 8; j++) {
            float d0 = mup[j][0] - mm0;
            float d1 = mup[j][1] - mm1;
            float d2 = mup[j][2] - mm2;
            float d3 = mup[j][3] - mm3;
            float q0 = fmaf(d0, d0, s0);
            float q1 = fmaf(d1, d1, s1);
            float q2 = fmaf(d2, d2, s2);
            float q3 = fmaf(d3, d3, s3);
            float q = (q0 * q1) * (q2 * q3);
            float v = __fdividef(wm, q);
            acc[j] += v;
            lhb[(size_t)j * KK + m] = to_tf32(v);
        }
    }

    __shared__ float red[8][9];
    int lane = threadIdx.x & 31, wid = threadIdx.x >> 5;
#pragma unroll
    for (int j = 0; j < 8; j++) {
        float v = acc[j];
#pragma unroll
        for (int o = 16; o > 0; o >>= 1) v += __shfl_xor_sync(0xffffffffu, v, o);
        if (lane == 0) red[wid][j] = v;
    }
    __syncthreads();
    if (threadIdx.x < 8) {
        float s = 0.0f;
#pragma unroll
        for (int w = 0; w < 8; w++) s += red[w][threadIdx.x];
        g_rinv[b * KK + p0 + threadIdx.x] = 1.0f / s;
    }
}

// ---------------- K3: A -> MMA-fragment-packed layout ----------------
// g_A[((b*256 + kb)*6 + mfg)*128 + lane*4] = float4{A(m,k), A(m+8,k), A(m,k+4), A(m+8,k+4)}
// with m = mfg*16 + (lane>>2), k = kb*8 + (lane&3); A(m,k) = tf32(x[b,m,k] * rinv[b,k]) or 0 pad.
__global__ void aprep_kernel(const float* __restrict__ x) {
    int kb = blockIdx.x, b = blockIdx.y;
    int t = threadIdx.x;           // 0..191
    int mfg = t >> 5, lane = t & 31;
    int g = lane >> 2, c = lane & 3;
    int m = mfg * 16 + g;
    int k = kb * 8 + c;

    float r0 = g_rinv[b * KK + k];
    float r1 = g_rinv[b * KK + k + 4];
    const float* xb = x + (size_t)b * DD * KK;

    float4 v = make_float4(0.0f, 0.0f, 0.0f, 0.0f);
    if (m < DD) {
        v.x = to_tf32(xb[(size_t)m * KK + k] * r0);
        v.z = to_tf32(xb[(size_t)m * KK + k + 4] * r1);
    }
    if (m + 8 < DD) {
        v.y = to_tf32(xb[(size_t)(m + 8) * KK + k] * r0);
        v.w = to_tf32(xb[(size_t)(m + 8) * KK + k + 4] * r1);
    }
    *(float4*)(g_A + (((size_t)(b * 256 + kb) * 6 + mfg) * 128 + lane * 4)) = v;
}

// ---------------- K4: tf32 mma.sync GEMM, 12 warps, frag-packed A, 3-stage pipe ----------------
// grid (KK/NTILE, KSPLIT, BN), 384 threads (12 warps = 3M x 4N), warp tile 32x32.
__global__ __launch_bounds__(384, 1) void gemm_mma() {
    extern __shared__ char dsm[];
    uint32_t sbase = smem_u32(dsm);

    int tid = threadIdx.x, wid = tid >> 5, lane = tid & 31;
    int nt = blockIdx.x, ks = blockIdx.y, b = blockIdx.z;
    int n0 = nt * NTILE;
    int kb0 = ks * (KSEG / 8);          // global kb base for this split

    int warpM = wid >> 2, warpN = wid & 3;   // 3 x 4
    int nbase = warpN * 32;
    int g = lane >> 2, c = lane & 3;

    const float* gA = g_A + (size_t)(b * 256 + kb0) * 6 * 128;
    const float* gB = g_lh + (size_t)b * KK * KK + (size_t)(ks * KSEG) * KK + n0;

    float acc[2][4][4];
#pragma unroll
    for (int i = 0; i < 2; i++)
#pragma unroll
        for (int j = 0; j < 4; j++)
#pragma unroll
            for (int q = 0; q < 4; q++) acc[i][j][q] = 0.0f;

    // stage loader: A = 768 float4 linear; B = 1024 float4 (32 rows x 32)
    auto stage = [&](int s) {
        int buf = s % NPIPE;
        uint32_t abase = sbase + buf * STGBYTES;
        uint32_t bbase = abase + ABYTES;
        const float4* srcA = (const float4*)(gA + (size_t)s * 4 * 6 * 128);
        const float* srcB = gB + (size_t)s * KCH * KK;
#pragma unroll
        for (int e = 0; e < 2; e++) {
            int i = tid + 384 * e;          // 0..767
            cpasync16(abase + i * 16, srcA + i);
        }
#pragma unroll
        for (int e = 0; e < 3; e++) {
            int i = tid + 384 * e;          // 0..1151, guard 1024
            if (i < 1024) {
                int k = i >> 5, cc = i & 31;
                cpasync16(bbase + (k * BSTRIDE + cc * 4) * 4, srcB + (size_t)k * KK + cc * 4);
            }
        }
        CP_COMMIT();
    };

    stage(0);
    stage(1);

    for (int s = 0; s < NSTG; s++) {
        if (s + 2 < NSTG) {
            CP_WAIT(1);
            __syncthreads();
            stage(s + 2);
        } else {
            CP_WAIT(0);
            __syncthreads();
        }

        int buf = s % NPIPE;
        const float4* A4 = (const float4*)(dsm + buf * STGBYTES);
        const float* B = (const float*)(dsm + buf * STGBYTES + ABYTES);

#pragma unroll
        for (int kb = 0; kb < KCH / 8; kb++) {
            uint32_t af[2][4], bf[4][2];
#pragma unroll
            for (int mf = 0; mf < 2; mf++) {
                float4 av = A4[(kb * 6 + warpM * 2 + mf) * 32 + lane];
                af[mf][0] = __float_as_uint(av.x);
                af[mf][1] = __float_as_uint(av.y);
                af[mf][2] = __float_as_uint(av.z);
                af[mf][3] = __float_as_uint(av.w);
            }
            const float* Br0 = B + (kb * 8 + c) * BSTRIDE;
            const float* Br1 = B + (kb * 8 + c + 4) * BSTRIDE;
#pragma unroll
            for (int nf = 0; nf < 4; nf++) {
                int n0i = nbase + nf * 8 + g;
                bf[nf][0] = __float_as_uint(Br0[n0i]);
                bf[nf][1] = __float_as_uint(Br1[n0i]);
            }
#pragma unroll
            for (int mf = 0; mf < 2; mf++)
#pragma unroll
                for (int nf = 0; nf < 4; nf++)
                    mma_tf32(acc[mf][nf], af[mf], bf[nf]);
        }
        __syncthreads();
    }

    // epilogue: write partials
    float* pp = g_part + ((size_t)(ks * BN + b) * MPAD) * KK + n0;
    int tig = lane & 3;
#pragma unroll
    for (int mf = 0; mf < 2; mf++) {
        int r0 = warpM * 32 + mf * 16 + g;
#pragma unroll
        for (int nf = 0; nf < 4; nf++) {
            int cc = nbase + nf * 8 + tig * 2;
            *(float2*)(pp + (size_t)r0 * KK + cc)       = make_float2(acc[mf][nf][0], acc[mf][nf][1]);
            *(float2*)(pp + (size_t)(r0 + 8) * KK + cc) = make_float2(acc[mf][nf][2], acc[mf][nf][3]);
        }
    }
}

// ---------------- K5: deterministic split-K reduce (float4) ----------------
__global__ void reduce_kernel(float* __restrict__ y) {
    int i = blockIdx.x * 256 + threadIdx.x;   // float4 index
    const int total = BN * DD * KK / 4;
    if (i >= total) return;
    int e = i * 4;
    int b = e / (DD * KK);
    int r = e - b * (DD * KK);
    int d = r / KK;
    int m = r - d * KK;
    size_t o = (((size_t)b * MPAD + d) * KK + m) / 4;
    const float4* p0 = (const float4*)g_part;
    const float4* p1 = (const float4*)(g_part + (size_t)BN * MPAD * KK);
    float4 a = p0[o], bb = p1[o];
    float4 out = make_float4(a.x + bb.x, a.y + bb.y, a.z + bb.z, a.w + bb.w);
    ((float4*)y)[i] = out;
}

// ---------------- launch ----------------
extern "C" void kernel_launch(void* const* d_in, const int* in_sizes, int n_in,
                              void* d_out, int out_size) {
    const float* x   = (const float*)d_in[0];  // (B, D, K)
    const float* pi  = (const float*)d_in[1];  // (B, 1, K)
    const float* mu  = (const float*)d_in[2];  // (B, ND, K)
    const float* sig = (const float*)d_in[3];  // (B, ND, K)
    float* y = (float*)d_out;                  // (B, D, K)

    cudaFuncSetAttribute(gemm_mma, cudaFuncAttributeMaxDynamicSharedMemorySize, DYN_SMEM);

    prep_kernel<<<(BN * KK + 255) / 256, 256>>>(pi, sig);
    lh_kernel<<<BN * (KK / 8), 256>>>(mu);
    aprep_kernel<<<dim3(KK / 8, BN), 192>>>(x);
    gemm_mma<<<dim3(KK / NTILE, KSPLIT, BN), 384, DYN_SMEM>>>();
    reduce_kernel<<<(BN * DD * KK / 4 + 255) / 256, 256>>>(y);
}